// round 10
// baseline (speedup 1.0000x reference)
#include <cuda_runtime.h>
#include <cuda_bf16.h>
#include <cstdint>

// Embedding gather: out[s, :] = weights[x[s], :]
// x: [8192] int32, weights: [49408, 768] fp32, out: [8192, 768] fp32
//
// Geometry = best-known (R2): U=8 rows/CTA, 192 threads, 16 B/thread.
// Added L2 residency control via createpolicy + cache_hint (works on 128-bit
// accesses, unlike bare evict_last):
//   - weights loads: evict_last  -> retain gather set across graph replays
//   - output stores: evict_first -> dirty lines drain early, never re-read

#define SEQ 8192
#define DIM 768
#define VEC (DIM / 4)   // 192 float4 per row
#define U   8           // rows per CTA

__global__ void __launch_bounds__(VEC) embed_gather_kernel(
    const int* __restrict__ x,
    const float4* __restrict__ weights,   // [VOCAB, VEC]
    float4* __restrict__ out)             // [SEQ, VEC]
{
    const int t  = threadIdx.x;
    const int s0 = blockIdx.x * U;

    uint64_t pol_keep, pol_drop;
    asm("createpolicy.fractional.L2::evict_last.b64 %0, 1.0;"  : "=l"(pol_keep));
    asm("createpolicy.fractional.L2::evict_first.b64 %0, 1.0;" : "=l"(pol_drop));

    int rows[U];
#pragma unroll
    for (int u = 0; u < U; u++)
        rows[u] = __ldg(&x[s0 + u]);

    float4 v[U];
#pragma unroll
    for (int u = 0; u < U; u++) {
        const float4* p = &weights[(size_t)rows[u] * VEC + t];
        asm("ld.global.nc.L2::cache_hint.v4.f32 {%0,%1,%2,%3}, [%4], %5;"
            : "=f"(v[u].x), "=f"(v[u].y), "=f"(v[u].z), "=f"(v[u].w)
            : "l"(p), "l"(pol_keep));
    }

#pragma unroll
    for (int u = 0; u < U; u++) {
        float4* p = &out[(size_t)(s0 + u) * VEC + t];
        asm volatile("st.global.L2::cache_hint.v4.f32 [%0], {%1,%2,%3,%4}, %5;"
                     :: "l"(p), "f"(v[u].x), "f"(v[u].y), "f"(v[u].z), "f"(v[u].w),
                        "l"(pol_drop)
                     : "memory");
    }
}

extern "C" void kernel_launch(void* const* d_in, const int* in_sizes, int n_in,
                              void* d_out, int out_size) {
    const int*    x = (const int*)d_in[0];
    const float4* w = (const float4*)d_in[1];
    float4*       o = (float4*)d_out;
    embed_gather_kernel<<<SEQ / U, VEC>>>(x, w, o);
}

// round 11
// speedup vs baseline: 1.1901x; 1.1901x over previous
#include <cuda_runtime.h>
#include <cuda_bf16.h>
#include <cstdint>

// Embedding gather via bulk-DMA, parallel drain: out[s,:] = weights[x[s],:]
// x: [8192] int32, weights: [49408, 768] fp32, out: [8192, 768] fp32
//
// Best-known geometry (R5): 8 rows/CTA, grid=1024, 24.6 KB smem.
// Change vs R5: threads 0-7 each own one row end-to-end (own mbarrier, own
// 3072 B buffer, own bulk_group) so the 8 mbarrier waits + bulk stores drain
// in parallel instead of a serialized 8-step driver loop.

#define SEQ       8192
#define ROW_BYTES 3072
#define RPC       8            // rows per CTA == active threads
#define GRID      (SEQ / RPC)  // 1024

__device__ __forceinline__ uint32_t smem_u32(const void* p) {
    uint32_t a;
    asm("{ .reg .u64 t; cvta.to.shared.u64 t, %1; cvt.u32.u64 %0, t; }"
        : "=r"(a) : "l"(p));
    return a;
}

__global__ void __launch_bounds__(32) embed_bulk_kernel(
    const int* __restrict__ x,
    const char* __restrict__ weights,
    char* __restrict__ out)
{
    __shared__ __align__(128) char buf[RPC][ROW_BYTES];
    __shared__ __align__(8)  unsigned long long mbar[RPC];

    const int t = threadIdx.x;
    if (t >= RPC) return;          // 8 owner threads; rest exit

    const int s  = blockIdx.x * RPC + t;
    const uint32_t mb  = smem_u32(&mbar[t]);
    const uint32_t bf  = smem_u32(&buf[t][0]);

    const int row = __ldg(&x[s]);

    // Own mbarrier init + async-proxy fence (each thread touches only its own).
    asm volatile("mbarrier.init.shared.b64 [%0], 1;" :: "r"(mb) : "memory");
    asm volatile("fence.proxy.async.shared::cta;" ::: "memory");

    // Issue this thread's 3072 B row load; 8 copies in flight per CTA at once.
    asm volatile("mbarrier.arrive.expect_tx.shared.b64 _, [%0], %1;"
                 :: "r"(mb), "r"((uint32_t)ROW_BYTES) : "memory");
    asm volatile(
        "cp.async.bulk.shared::cta.global.mbarrier::complete_tx::bytes "
        "[%0], [%1], %2, [%3];"
        :: "r"(bf),
           "l"(weights + (size_t)row * ROW_BYTES),
           "r"((uint32_t)ROW_BYTES),
           "r"(mb)
        : "memory");

    // Wait own row (parallel across the 8 owners), then bulk-store it out.
    asm volatile(
        "{\n\t"
        ".reg .pred P1;\n\t"
        "WL_%=:\n\t"
        "mbarrier.try_wait.parity.acquire.cta.shared::cta.b64 P1, [%0], 0, 0x989680;\n\t"
        "@P1 bra.uni WD_%=;\n\t"
        "bra.uni WL_%=;\n\t"
        "WD_%=:\n\t"
        "}" :: "r"(mb) : "memory");
    asm volatile("fence.proxy.async.shared::cta;" ::: "memory");
    asm volatile(
        "cp.async.bulk.global.shared::cta.bulk_group [%0], [%1], %2;"
        :: "l"(out + (size_t)s * ROW_BYTES),
           "r"(bf),
           "r"((uint32_t)ROW_BYTES)
        : "memory");
    asm volatile("cp.async.bulk.commit_group;" ::: "memory");
    asm volatile("cp.async.bulk.wait_group 0;" ::: "memory");
}

extern "C" void kernel_launch(void* const* d_in, const int* in_sizes, int n_in,
                              void* d_out, int out_size) {
    const int*  x = (const int*)d_in[0];
    const char* w = (const char*)d_in[1];
    char*       o = (char*)d_out;
    embed_bulk_kernel<<<GRID, 32>>>(x, w, o);
}